// round 1
// baseline (speedup 1.0000x reference)
#include <cuda_runtime.h>
#include <math.h>
#include <stdint.h>

// Problem dims (fixed by reference setup_inputs)
#define BB   8
#define TT   2048
#define CC   1024
#define MM   (BB * TT)        // 16384 rows
#define KK   CC               // 1024

// GEMM tiling
#define Bb_M 128
#define Bb_N 128
#define Bb_K 16

// Scratch: cos/sin interleaved + amp (device globals; no runtime allocation)
__device__ float2 g_cs [(size_t)MM * CC];
__device__ float  g_amp[(size_t)MM * CC];

__device__ __forceinline__ float tanh_precise(float z) {
    // 1 - 2/(e^{2z}+1): monotone, saturates correctly at +/-1 even on overflow,
    // abs err ~1e-7 with expf (fast-math __expf is ~3e-7 rel — still fine).
    return 1.0f - 2.0f / (expf(2.0f * z) + 1.0f);
}

__global__ __launch_bounds__(256)
void fused_gemm_act(const float* __restrict__ X,
                    const float* __restrict__ Wp, const float* __restrict__ bp,
                    const float* __restrict__ Wa, const float* __restrict__ ba)
{
    __shared__ float As[2][Bb_K][Bb_M + 4];
    __shared__ float Bs[2][Bb_K][Bb_N + 4];

    const int tid    = threadIdx.x;
    const int m0     = blockIdx.x * Bb_M;
    const int nBlkC  = CC / Bb_N;                 // 8
    const int is_amp = (blockIdx.y >= nBlkC);
    const int n0     = (is_amp ? (int)blockIdx.y - nBlkC : (int)blockIdx.y) * Bb_N;

    const float* __restrict__ W    = is_amp ? Wa : Wp;
    const float* __restrict__ bias = is_amp ? ba : bp;

    // Loader mapping: 256 threads, tile = 128 rows x 16 k = 512 float4 -> 2 per thread
    const int lrow = tid >> 2;          // 0..63
    const int lk4  = (tid & 3) * 4;     // k offset 0,4,8,12

    // Compute mapping: 16x16 threads, each 8x8
    const int ty  = tid >> 4;
    const int tx  = tid & 15;
    const int tm0 = ty * 8;
    const int tn0 = tx * 8;

    const float* __restrict__ Xp = X + (size_t)m0 * KK;
    const float* __restrict__ Wn = W + (size_t)n0 * KK;

    float acc[8][8];
    #pragma unroll
    for (int i = 0; i < 8; i++)
        #pragma unroll
        for (int j = 0; j < 8; j++) acc[i][j] = 0.0f;

    // Prologue: load k-tile 0 into buffer 0
    {
        #pragma unroll
        for (int i = 0; i < 2; i++) {
            const int r = lrow + i * 64;
            float4 va = *(const float4*)(Xp + (size_t)r * KK + lk4);
            As[0][lk4 + 0][r] = va.x; As[0][lk4 + 1][r] = va.y;
            As[0][lk4 + 2][r] = va.z; As[0][lk4 + 3][r] = va.w;
            float4 vb = *(const float4*)(Wn + (size_t)r * KK + lk4);
            Bs[0][lk4 + 0][r] = vb.x; Bs[0][lk4 + 1][r] = vb.y;
            Bs[0][lk4 + 2][r] = vb.z; Bs[0][lk4 + 3][r] = vb.w;
        }
    }
    __syncthreads();

    const int NT = KK / Bb_K;   // 64
    int buf = 0;
    for (int kt = 0; kt < NT; kt++) {
        float4 pva[2], pvb[2];
        const bool more = (kt + 1 < NT);
        if (more) {
            const int k0 = (kt + 1) * Bb_K;
            #pragma unroll
            for (int i = 0; i < 2; i++) {
                const int r = lrow + i * 64;
                pva[i] = *(const float4*)(Xp + (size_t)r * KK + k0 + lk4);
                pvb[i] = *(const float4*)(Wn + (size_t)r * KK + k0 + lk4);
            }
        }

        #pragma unroll
        for (int k = 0; k < Bb_K; k++) {
            float a[8], b[8];
            #pragma unroll
            for (int i = 0; i < 8; i++) a[i] = As[buf][k][tm0 + i];
            #pragma unroll
            for (int j = 0; j < 8; j++) b[j] = Bs[buf][k][tn0 + j];
            #pragma unroll
            for (int i = 0; i < 8; i++)
                #pragma unroll
                for (int j = 0; j < 8; j++)
                    acc[i][j] = fmaf(a[i], b[j], acc[i][j]);
        }

        if (more) {
            const int nb = buf ^ 1;
            #pragma unroll
            for (int i = 0; i < 2; i++) {
                const int r = lrow + i * 64;
                As[nb][lk4 + 0][r] = pva[i].x; As[nb][lk4 + 1][r] = pva[i].y;
                As[nb][lk4 + 2][r] = pva[i].z; As[nb][lk4 + 3][r] = pva[i].w;
                Bs[nb][lk4 + 0][r] = pvb[i].x; Bs[nb][lk4 + 1][r] = pvb[i].y;
                Bs[nb][lk4 + 2][r] = pvb[i].z; Bs[nb][lk4 + 3][r] = pvb[i].w;
            }
            __syncthreads();
            buf = nb;
        }
    }

    // Epilogue
    const float PI_F = 3.14159265358979f;
    const float STEP = 1.0471975511965976f;   // pi/3 (rounds to f32)
    const float TOL  = 0.15f;

    float bv[8];
    #pragma unroll
    for (int j = 0; j < 8; j++) bv[j] = bias[n0 + tn0 + j];

    if (!is_amp) {
        #pragma unroll
        for (int i = 0; i < 8; i++) {
            const int m = m0 + tm0 + i;
            float2* dst = g_cs + (size_t)m * CC + (n0 + tn0);
            float4 pack[4];
            #pragma unroll
            for (int j = 0; j < 8; j++) {
                float z   = acc[i][j] + bv[j];
                float ang = tanh_precise(z) * PI_F;
                float nearest = rintf(ang / STEP) * STEP;
                float a   = (fabsf(ang - nearest) < TOL) ? nearest : ang;
                float sv, cv;
                sincosf(a, &sv, &cv);
                if (j & 1) { pack[j >> 1].z = cv; pack[j >> 1].w = sv; }
                else       { pack[j >> 1].x = cv; pack[j >> 1].y = sv; }
            }
            #pragma unroll
            for (int p = 0; p < 4; p++)
                *(float4*)(dst + 2 * p) = pack[p];
        }
    } else {
        #pragma unroll
        for (int i = 0; i < 8; i++) {
            const int m = m0 + tm0 + i;
            float* dst = g_amp + (size_t)m * CC + (n0 + tn0);
            float4 pack[2];
            #pragma unroll
            for (int j = 0; j < 8; j++) {
                float z = acc[i][j] + bv[j];
                ((float*)pack)[j] = 1.0f / (1.0f + expf(-z));
            }
            *(float4*)(dst + 0) = pack[0];
            *(float4*)(dst + 4) = pack[1];
        }
    }
}

// Sequential scan over T. One thread per (b, c) chain; loads batched (unroll 8)
// for MLP; fully coalesced across c within a warp.
__global__ __launch_bounds__(64)
void scan_kernel(const float* __restrict__ state_in,
                 float* __restrict__ out,
                 float* __restrict__ state_out)
{
    const int idx = blockIdx.x * 64 + threadIdx.x;   // 0..8191 over (b, c)
    const int b = idx >> 10;
    const int c = idx & (CC - 1);

    float s = state_in[idx];

    const float2* __restrict__ pcs = g_cs  + (size_t)b * TT * CC + c;
    const float*  __restrict__ pa  = g_amp + (size_t)b * TT * CC + c;
    float*        __restrict__ po  = out   + (size_t)b * TT * CC + c;

    for (int t = 0; t < TT; t += 8) {
        float2 v[8]; float a[8];
        #pragma unroll
        for (int u = 0; u < 8; u++) {
            v[u] = pcs[(size_t)(t + u) * CC];
            a[u] = pa [(size_t)(t + u) * CC];
        }
        #pragma unroll
        for (int u = 0; u < 8; u++) {
            // s' = clip(cos*s - sin*(1-s), -1, 1) = clip((cos+sin)*s - sin)
            s = fminf(fmaxf(fmaf(v[u].x + v[u].y, s, -v[u].y), -1.0f), 1.0f);
            po[(size_t)(t + u) * CC] = a[u] * s;
        }
    }
    if (state_out) state_out[idx] = s;
}

extern "C" void kernel_launch(void* const* d_in, const int* in_sizes, int n_in,
                              void* d_out, int out_size)
{
    const float* x  = (const float*)d_in[0];
    const float* st = (const float*)d_in[1];
    const float* Wp = (const float*)d_in[2];
    const float* bp = (const float*)d_in[3];
    const float* Wa = (const float*)d_in[4];
    const float* ba = (const float*)d_in[5];
    float* out = (float*)d_out;

    const size_t BTC = (size_t)MM * CC;
    float* state_out = ((size_t)out_size >= BTC + (size_t)BB * CC)
                       ? out + BTC : nullptr;

    dim3 grid(MM / Bb_M, 2 * CC / Bb_N);   // (128, 16)
    fused_gemm_act<<<grid, 256>>>(x, Wp, bp, Wa, ba);
    scan_kernel<<<(BB * CC) / 64, 64>>>(st, out, state_out);
}

// round 6
// speedup vs baseline: 2.1232x; 2.1232x over previous
#include <cuda_runtime.h>
#include <cuda_bf16.h>
#include <math.h>
#include <stdint.h>

// ---------------------------------------------------------------------------
// Problem dims (fixed by reference setup_inputs)
// ---------------------------------------------------------------------------
#define BBATCH 8
#define TSEQ   2048
#define CDIM   1024
#define MROWS  (BBATCH * TSEQ)      // 16384
#define KPACK  2048                 // packed per row: 32 chunks x (32 hi | 32 lo) bf16
#define NCHUNK 32                   // 32 chunks of real-K 32

// GEMM tile: CTA 128x128, 8 warps of 64x32
#define TM 128
#define TN 128
#define STAGE_BYTES 32768           // A tile 16KB + B tile 16KB
#define NSTAGE 3
#define SMEM_DYN (NSTAGE * STAGE_BYTES)

// ---------------------------------------------------------------------------
// Device scratch (no runtime allocation allowed)
// ---------------------------------------------------------------------------
__device__ __nv_bfloat16 g_Xp [(size_t)MROWS * KPACK];   // 64 MB packed X (hi|lo)
__device__ __nv_bfloat16 g_Wp2[(size_t)CDIM * KPACK];    // 4 MB packed W_phi
__device__ __nv_bfloat16 g_Wa2[(size_t)CDIM * KPACK];    // 4 MB packed W_amp
__device__ float2 g_cs [(size_t)MROWS * CDIM];           // (cos+sin, sin)
__device__ float  g_amp[(size_t)MROWS * CDIM];

// ---------------------------------------------------------------------------
// PTX helpers (sm_80-era instructions only: valid on compute_100 target)
// ---------------------------------------------------------------------------
__device__ __forceinline__ uint32_t smem_u32(const void* p) {
    uint32_t a;
    asm("{ .reg .u64 t; cvta.to.shared.u64 t, %1; cvt.u32.u64 %0, t; }"
        : "=r"(a) : "l"(p));
    return a;
}
__device__ __forceinline__ void cp16(uint32_t dst, const void* src) {
    asm volatile("cp.async.cg.shared.global [%0], [%1], 16;" :: "r"(dst), "l"(src));
}
__device__ __forceinline__ void cp_commit() {
    asm volatile("cp.async.commit_group;" ::: "memory");
}
template<int N> __device__ __forceinline__ void cp_wait() {
    asm volatile("cp.async.wait_group %0;" :: "n"(N) : "memory");
}
__device__ __forceinline__ void ldsm4(uint32_t& r0, uint32_t& r1,
                                      uint32_t& r2, uint32_t& r3, uint32_t addr) {
    asm volatile("ldmatrix.sync.aligned.m8n8.x4.shared.b16 {%0,%1,%2,%3}, [%4];"
                 : "=r"(r0), "=r"(r1), "=r"(r2), "=r"(r3) : "r"(addr));
}
__device__ __forceinline__ void mma16816(float* c, const uint32_t* a, const uint32_t* b) {
    asm volatile("mma.sync.aligned.m16n8k16.row.col.f32.bf16.bf16.f32 "
                 "{%0,%1,%2,%3}, {%4,%5,%6,%7}, {%8,%9}, {%0,%1,%2,%3};"
                 : "+f"(c[0]), "+f"(c[1]), "+f"(c[2]), "+f"(c[3])
                 : "r"(a[0]), "r"(a[1]), "r"(a[2]), "r"(a[3]),
                   "r"(b[0]), "r"(b[1]));
}
// swizzled smem offset within a [row][128B] tile (SW128-style: seg ^ (row&7))
__device__ __forceinline__ uint32_t swz(int row, int byteoff) {
    return (uint32_t)(row * 128 + ((((byteoff >> 4) ^ (row & 7)) << 4) | (byteoff & 15)));
}

// ---------------------------------------------------------------------------
// Conversion kernels: fp32 -> packed bf16 (hi|lo per 32-K chunk)
// ---------------------------------------------------------------------------
__global__ __launch_bounds__(256)
void convert_x(const float* __restrict__ x)
{
    int g  = blockIdx.x * 256 + threadIdx.x;
    int m  = g >> 7;
    int k0 = (g & 127) << 3;
    const float* src = x + (size_t)m * CDIM + k0;
    float4 v0 = *(const float4*)(src);
    float4 v1 = *(const float4*)(src + 4);
    float f[8] = {v0.x, v0.y, v0.z, v0.w, v1.x, v1.y, v1.z, v1.w};
    __nv_bfloat16 h[8], l[8];
    #pragma unroll
    for (int i = 0; i < 8; i++) {
        h[i] = __float2bfloat16_rn(f[i]);
        l[i] = __float2bfloat16_rn(f[i] - __bfloat162float(h[i]));
    }
    size_t base = (size_t)m * KPACK + (size_t)((k0 >> 5) << 6) + (k0 & 31);
    *(uint4*)&g_Xp[base]      = *(uint4*)h;
    *(uint4*)&g_Xp[base + 32] = *(uint4*)l;
}

__global__ __launch_bounds__(256)
void convert_w(const float* __restrict__ Wp, const float* __restrict__ Wa)
{
    const float* W = blockIdx.y ? Wa : Wp;
    __nv_bfloat16* D = blockIdx.y ? g_Wa2 : g_Wp2;
    int g  = blockIdx.x * 256 + threadIdx.x;
    int n  = g >> 7;
    int k0 = (g & 127) << 3;
    const float* src = W + (size_t)n * CDIM + k0;
    float4 v0 = *(const float4*)(src);
    float4 v1 = *(const float4*)(src + 4);
    float f[8] = {v0.x, v0.y, v0.z, v0.w, v1.x, v1.y, v1.z, v1.w};
    __nv_bfloat16 h[8], l[8];
    #pragma unroll
    for (int i = 0; i < 8; i++) {
        h[i] = __float2bfloat16_rn(f[i]);
        l[i] = __float2bfloat16_rn(f[i] - __bfloat162float(h[i]));
    }
    size_t base = (size_t)n * KPACK + (size_t)((k0 >> 5) << 6) + (k0 & 31);
    *(uint4*)&D[base]      = *(uint4*)h;
    *(uint4*)&D[base + 32] = *(uint4*)l;
}

// ---------------------------------------------------------------------------
// bf16 3-split GEMM via mma.sync (HMMA) + fused activation epilogue.
// grid = (128, 16): y<8 -> phi tile (n0 = y*128), y>=8 -> amp (n0 = (y-8)*128)
// ---------------------------------------------------------------------------
__device__ __forceinline__ void load_chunk(int c, uint32_t smem,
                                           const __nv_bfloat16* Apk,
                                           const __nv_bfloat16* Bpk,
                                           int tid)
{
    const uint32_t a_base = smem + (c % NSTAGE) * STAGE_BYTES;
    const uint32_t b_base = a_base + 16384;
    const char* ag = (const char*)Apk + (size_t)c * 128;   // row stride 4096B
    const char* bg = (const char*)Bpk + (size_t)c * 128;
    #pragma unroll
    for (int i = 0; i < 4; i++) {                          // A: 1024 x 16B segs
        int seg = tid + i * 256;
        int r = seg >> 3, s = seg & 7;
        cp16(a_base + (uint32_t)(r * 128 + ((s ^ (r & 7)) << 4)),
             ag + (size_t)r * 4096 + s * 16);
    }
    #pragma unroll
    for (int i = 0; i < 4; i++) {                          // B: 1024 x 16B segs
        int seg = tid + i * 256;
        int r = seg >> 3, s = seg & 7;
        cp16(b_base + (uint32_t)(r * 128 + ((s ^ (r & 7)) << 4)),
             bg + (size_t)r * 4096 + s * 16);
    }
    cp_commit();
}

__global__ __launch_bounds__(256, 2)
void gemm_hmma_split(const float* __restrict__ bp, const float* __restrict__ ba)
{
    extern __shared__ char smraw[];
    const uint32_t smem = smem_u32(smraw);

    const int tid = threadIdx.x;
    const int wid = tid >> 5;
    const int lid = tid & 31;
    const int m0  = blockIdx.x * TM;
    const int is_amp = (blockIdx.y >= 8);
    const int n0  = (is_amp ? (int)blockIdx.y - 8 : (int)blockIdx.y) * TN;

    const int wm = (wid & 1) * 64;     // warp m-offset
    const int wn = (wid >> 1) * 32;    // warp n-offset

    const __nv_bfloat16* Apk = g_Xp + (size_t)m0 * KPACK;
    const __nv_bfloat16* Bpk = (is_amp ? g_Wa2 : g_Wp2) + (size_t)n0 * KPACK;
    const float* bias = is_amp ? ba : bp;

    // ldmatrix per-lane row/seg components (within x4 group g = lid>>3)
    const int g8 = lid >> 3;
    const int r8 = lid & 7;
    // A: matrices {m0-7/k0-7, m8-15/k0-7, m0-7/k8-15, m8-15/k8-15} = {a0,a1,a2,a3}
    const int aRow = wm + ((g8 & 1) << 3) + r8;
    const int aSeg = (g8 >> 1) << 4;
    // B: matrices {n0-7/k0-7, n0-7/k8-15, n8-15/k0-7, n8-15/k8-15}
    const int bRow = wn + ((g8 >> 1) << 3) + r8;
    const int bSeg = (g8 & 1) << 4;

    float acc[4][4][4];
    #pragma unroll
    for (int mt = 0; mt < 4; mt++)
        #pragma unroll
        for (int nt = 0; nt < 4; nt++)
            #pragma unroll
            for (int i = 0; i < 4; i++) acc[mt][nt][i] = 0.0f;

    load_chunk(0, smem, Apk, Bpk, tid);
    load_chunk(1, smem, Apk, Bpk, tid);

    for (int c = 0; c < NCHUNK; c++) {
        if (c < NCHUNK - 1) cp_wait<1>(); else cp_wait<0>();
        __syncthreads();
        if (c + 2 < NCHUNK) load_chunk(c + 2, smem, Apk, Bpk, tid);

        const uint32_t aBase = smem + (c % NSTAGE) * STAGE_BYTES;
        const uint32_t bBase = aBase + 16384;

        #pragma unroll
        for (int ks = 0; ks < 2; ks++) {
            const int kbh = ks * 32;        // hi bytes [0,64)
            const int kbl = 64 + ks * 32;   // lo bytes [64,128)

            uint32_t Bh[2][4], Bl[2][4];
            #pragma unroll
            for (int np = 0; np < 2; np++) {
                int row = bRow + np * 16;
                ldsm4(Bh[np][0], Bh[np][1], Bh[np][2], Bh[np][3],
                      bBase + swz(row, kbh + bSeg));
                ldsm4(Bl[np][0], Bl[np][1], Bl[np][2], Bl[np][3],
                      bBase + swz(row, kbl + bSeg));
            }

            #pragma unroll
            for (int mt = 0; mt < 4; mt++) {
                int row = aRow + mt * 16;
                uint32_t Ah[4], Al[4];
                ldsm4(Ah[0], Ah[1], Ah[2], Ah[3], aBase + swz(row, kbh + aSeg));
                ldsm4(Al[0], Al[1], Al[2], Al[3], aBase + swz(row, kbl + aSeg));
                #pragma unroll
                for (int nt = 0; nt < 4; nt++) {
                    const uint32_t* bh = &Bh[nt >> 1][(nt & 1) * 2];
                    const uint32_t* bl = &Bl[nt >> 1][(nt & 1) * 2];
                    mma16816(acc[mt][nt], Ah, bh);   // Ah*Bh
                    mma16816(acc[mt][nt], Ah, bl);   // Ah*Bl
                    mma16816(acc[mt][nt], Al, bh);   // Al*Bh
                }
            }
        }
    }

    // ---- register-direct fused activation epilogue --------------------------
    const float PI_F     = 3.14159265358979f;
    const float STEP     = 1.0471975511965976f;    // pi/3
    const float INV_STEP = 0.9549296585513720f;    // 3/pi
    const float TOL      = 0.15f;

    #pragma unroll
    for (int mt = 0; mt < 4; mt++) {
        #pragma unroll
        for (int nt = 0; nt < 4; nt++) {
            const int col = n0 + wn + nt * 8 + (lid & 3) * 2;
            const float2 bv = *(const float2*)&bias[col];
            #pragma unroll
            for (int h = 0; h < 2; h++) {
                const int m = m0 + wm + mt * 16 + (lid >> 2) + h * 8;
                float z0 = acc[mt][nt][h * 2 + 0] + bv.x;
                float z1 = acc[mt][nt][h * 2 + 1] + bv.y;
                if (!is_amp) {
                    // tanh via exp (accurate), gate, sincos
                    float t0 = 1.0f - __fdividef(2.0f, __expf(2.0f * z0) + 1.0f);
                    float t1 = 1.0f - __fdividef(2.0f, __expf(2.0f * z1) + 1.0f);
                    float a0 = t0 * PI_F, a1 = t1 * PI_F;
                    float n0f = rintf(a0 * INV_STEP) * STEP;
                    float n1f = rintf(a1 * INV_STEP) * STEP;
                    a0 = (fabsf(a0 - n0f) < TOL) ? n0f : a0;
                    a1 = (fabsf(a1 - n1f) < TOL) ? n1f : a1;
                    float s0 = __sinf(a0), c0 = __cosf(a0);
                    float s1 = __sinf(a1), c1 = __cosf(a1);
                    float4 w = make_float4(c0 + s0, s0, c1 + s1, s1);
                    *(float4*)&g_cs[(size_t)m * CDIM + col] = w;
                } else {
                    float s0 = __fdividef(1.0f, 1.0f + __expf(-z0));
                    float s1 = __fdividef(1.0f, 1.0f + __expf(-z1));
                    *(float2*)&g_amp[(size_t)m * CDIM + col] = make_float2(s0, s1);
                }
            }
        }
    }
}

// ---------------------------------------------------------------------------
// Sequential scan over T. One thread per (b, c) chain. Explicit double-buffer
// prefetch: loads for batch t+8 are issued before the dependent compute of
// batch t, so DRAM latency is overlapped with the recurrence chain.
// g_cs = (cos+sin, sin)  ->  s' = clip(fma(v.x, s, -v.y), -1, 1)
// ---------------------------------------------------------------------------
__global__ __launch_bounds__(64)
void scan_kernel(const float* __restrict__ state_in,
                 float* __restrict__ out,
                 float* __restrict__ state_out)
{
    const int idx = blockIdx.x * 64 + threadIdx.x;   // 0..8191 over (b, c)
    const int b = idx >> 10;
    const int c = idx & (CDIM - 1);

    float s = state_in[idx];

    const float2* __restrict__ pcs = g_cs  + (size_t)b * TSEQ * CDIM + c;
    const float*  __restrict__ pa  = g_amp + (size_t)b * TSEQ * CDIM + c;
    float*        __restrict__ po  = out   + (size_t)b * TSEQ * CDIM + c;

    float2 vA[8], vB[8];
    float  aA[8], aB[8];

    #pragma unroll
    for (int u = 0; u < 8; u++) {
        vA[u] = pcs[(size_t)u * CDIM];
        aA[u] = pa [(size_t)u * CDIM];
    }

    for (int t = 0; t < TSEQ; t += 16) {
        // prefetch batch t+8 into B
        #pragma unroll
        for (int u = 0; u < 8; u++) {
            vB[u] = pcs[(size_t)(t + 8 + u) * CDIM];
            aB[u] = pa [(size_t)(t + 8 + u) * CDIM];
        }
        // compute batch t from A
        #pragma unroll
        for (int u = 0; u < 8; u++) {
            s = fminf(fmaxf(fmaf(vA[u].x, s, -vA[u].y), -1.0f), 1.0f);
            po[(size_t)(t + u) * CDIM] = aA[u] * s;
        }
        // prefetch batch t+16 into A
        if (t + 16 < TSEQ) {
            #pragma unroll
            for (int u = 0; u < 8; u++) {
                vA[u] = pcs[(size_t)(t + 16 + u) * CDIM];
                aA[u] = pa [(size_t)(t + 16 + u) * CDIM];
            }
        }
        // compute batch t+8 from B
        #pragma unroll
        for (int u = 0; u < 8; u++) {
            s = fminf(fmaxf(fmaf(vB[u].x, s, -vB[u].y), -1.0f), 1.0f);
            po[(size_t)(t + 8 + u) * CDIM] = aB[u] * s;
        }
    }
    if (state_out) state_out[idx] = s;
}

// ---------------------------------------------------------------------------
extern "C" void kernel_launch(void* const* d_in, const int* in_sizes, int n_in,
                              void* d_out, int out_size)
{
    const float* x  = (const float*)d_in[0];
    const float* st = (const float*)d_in[1];
    const float* Wp = (const float*)d_in[2];
    const float* bp = (const float*)d_in[3];
    const float* Wa = (const float*)d_in[4];
    const float* ba = (const float*)d_in[5];
    float* out = (float*)d_out;

    const size_t BTC = (size_t)MROWS * CDIM;
    float* state_out = ((size_t)out_size >= BTC + (size_t)BBATCH * CDIM)
                       ? out + BTC : nullptr;

    // Unconditional (no static guards): idempotent, not a stream op, capture-safe.
    cudaFuncSetAttribute(gemm_hmma_split,
                         cudaFuncAttributeMaxDynamicSharedMemorySize, SMEM_DYN);

    convert_x<<<8192, 256>>>(x);
    convert_w<<<dim3(512, 2), 256>>>(Wp, Wa);
    gemm_hmma_split<<<dim3(MROWS / TM, 16), 256, SMEM_DYN>>>(bp, ba);
    scan_kernel<<<(BBATCH * CDIM) / 64, 64>>>(st, out, state_out);
}

// round 9
// speedup vs baseline: 2.8195x; 1.3280x over previous
#include <cuda_runtime.h>
#include <cuda_fp16.h>
#include <math.h>
#include <stdint.h>

// ---------------------------------------------------------------------------
// Problem dims (fixed by reference setup_inputs)
// ---------------------------------------------------------------------------
#define BBATCH 8
#define TSEQ   2048
#define CDIM   1024
#define MROWS  (BBATCH * TSEQ)      // 16384
#define KPACK  2048                 // packed per row: 32 chunks x (32 hi | 32 lo) fp16
#define NCHUNK 32                   // 32 chunks of real-K 32
#define LO_SCALE   4096.0f          // lo parts scaled by 2^12
#define LO_UNSCALE 2.44140625e-4f   // 2^-12 applied to accL

// GEMM tile: CTA 128x128, 16 warps of 32x32, 512 threads
#define TM 128
#define TN 128
#define STAGE_BYTES 32768           // A tile 16KB + B tile 16KB
#define NSTAGE 5
#define SMEM_DYN (NSTAGE * STAGE_BYTES)   // 160 KB

// ---------------------------------------------------------------------------
// Device scratch (no runtime allocation allowed)
// ---------------------------------------------------------------------------
__device__ __half g_Xp [(size_t)MROWS * KPACK];   // 64 MB packed X (hi|lo*2^12)
__device__ __half g_Wp2[(size_t)CDIM * KPACK];    // 4 MB packed W_phi
__device__ __half g_Wa2[(size_t)CDIM * KPACK];    // 4 MB packed W_amp
__device__ float2 g_cs [(size_t)MROWS * CDIM];    // (cos+sin, sin)
__device__ float  g_amp[(size_t)MROWS * CDIM];

// ---------------------------------------------------------------------------
// PTX helpers (sm_80-era instructions only: valid on compute_100 target)
// ---------------------------------------------------------------------------
__device__ __forceinline__ uint32_t smem_u32(const void* p) {
    uint32_t a;
    asm("{ .reg .u64 t; cvta.to.shared.u64 t, %1; cvt.u32.u64 %0, t; }"
        : "=r"(a) : "l"(p));
    return a;
}
__device__ __forceinline__ void cp16(uint32_t dst, const void* src) {
    asm volatile("cp.async.cg.shared.global [%0], [%1], 16;" :: "r"(dst), "l"(src));
}
__device__ __forceinline__ void cp8(uint32_t dst, const void* src) {
    asm volatile("cp.async.ca.shared.global [%0], [%1], 8;" :: "r"(dst), "l"(src));
}
__device__ __forceinline__ void cp4(uint32_t dst, const void* src) {
    asm volatile("cp.async.ca.shared.global [%0], [%1], 4;" :: "r"(dst), "l"(src));
}
__device__ __forceinline__ void cp_commit() {
    asm volatile("cp.async.commit_group;" ::: "memory");
}
template<int N> __device__ __forceinline__ void cp_wait() {
    asm volatile("cp.async.wait_group %0;" :: "n"(N) : "memory");
}
__device__ __forceinline__ void ldsm4(uint32_t& r0, uint32_t& r1,
                                      uint32_t& r2, uint32_t& r3, uint32_t addr) {
    asm volatile("ldmatrix.sync.aligned.m8n8.x4.shared.b16 {%0,%1,%2,%3}, [%4];"
                 : "=r"(r0), "=r"(r1), "=r"(r2), "=r"(r3) : "r"(addr));
}
__device__ __forceinline__ void mma16816(float* c, const uint32_t* a, const uint32_t* b) {
    asm volatile("mma.sync.aligned.m16n8k16.row.col.f32.f16.f16.f32 "
                 "{%0,%1,%2,%3}, {%4,%5,%6,%7}, {%8,%9}, {%0,%1,%2,%3};"
                 : "+f"(c[0]), "+f"(c[1]), "+f"(c[2]), "+f"(c[3])
                 : "r"(a[0]), "r"(a[1]), "r"(a[2]), "r"(a[3]),
                   "r"(b[0]), "r"(b[1]));
}
// swizzled smem offset within a [row][128B] tile (SW128-style: seg ^ (row&7))
__device__ __forceinline__ uint32_t swz(int row, int byteoff) {
    return (uint32_t)(row * 128 + ((((byteoff >> 4) ^ (row & 7)) << 4) | (byteoff & 15)));
}

// ---------------------------------------------------------------------------
// Conversion kernels: fp32 -> packed fp16 (hi | lo*2^12 per 32-K chunk)
// ---------------------------------------------------------------------------
__global__ __launch_bounds__(256)
void convert_x(const float* __restrict__ x)
{
    int g  = blockIdx.x * 256 + threadIdx.x;
    int m  = g >> 7;
    int k0 = (g & 127) << 3;
    const float* src = x + (size_t)m * CDIM + k0;
    float4 v0 = *(const float4*)(src);
    float4 v1 = *(const float4*)(src + 4);
    float f[8] = {v0.x, v0.y, v0.z, v0.w, v1.x, v1.y, v1.z, v1.w};
    __align__(16) __half h[8];
    __align__(16) __half l[8];
    #pragma unroll
    for (int i = 0; i < 8; i++) {
        h[i] = __float2half_rn(f[i]);
        l[i] = __float2half_rn((f[i] - __half2float(h[i])) * LO_SCALE);
    }
    size_t base = (size_t)m * KPACK + (size_t)((k0 >> 5) << 6) + (k0 & 31);
    *(uint4*)&g_Xp[base]      = *(uint4*)h;
    *(uint4*)&g_Xp[base + 32] = *(uint4*)l;
}

__global__ __launch_bounds__(256)
void convert_w(const float* __restrict__ Wp, const float* __restrict__ Wa)
{
    const float* W = blockIdx.y ? Wa : Wp;
    __half* D = blockIdx.y ? g_Wa2 : g_Wp2;
    int g  = blockIdx.x * 256 + threadIdx.x;
    int n  = g >> 7;
    int k0 = (g & 127) << 3;
    const float* src = W + (size_t)n * CDIM + k0;
    float4 v0 = *(const float4*)(src);
    float4 v1 = *(const float4*)(src + 4);
    float f[8] = {v0.x, v0.y, v0.z, v0.w, v1.x, v1.y, v1.z, v1.w};
    __align__(16) __half h[8];
    __align__(16) __half l[8];
    #pragma unroll
    for (int i = 0; i < 8; i++) {
        h[i] = __float2half_rn(f[i]);
        l[i] = __float2half_rn((f[i] - __half2float(h[i])) * LO_SCALE);
    }
    size_t base = (size_t)n * KPACK + (size_t)((k0 >> 5) << 6) + (k0 & 31);
    *(uint4*)&D[base]      = *(uint4*)h;
    *(uint4*)&D[base + 32] = *(uint4*)l;
}

// ---------------------------------------------------------------------------
// fp16 3-split GEMM via mma.sync (HMMA) + fused activation epilogue.
// z = accH + 2^-12 * accL  (accL holds Ah*Bl' + Al'*Bh with lo' = lo*2^12)
// grid = (128, 16): y<8 -> phi tile (n0 = y*128), y>=8 -> amp (n0 = (y-8)*128)
// ---------------------------------------------------------------------------
__device__ __forceinline__ void load_chunk(int c, uint32_t smem,
                                           const __half* Apk,
                                           const __half* Bpk,
                                           int tid)
{
    const uint32_t a_base = smem + (c % NSTAGE) * STAGE_BYTES;
    const uint32_t b_base = a_base + 16384;
    const char* ag = (const char*)Apk + (size_t)c * 128;   // row stride 4096B
    const char* bg = (const char*)Bpk + (size_t)c * 128;
    #pragma unroll
    for (int i = 0; i < 2; i++) {                          // A: 1024 x 16B segs / 512 thr
        int seg = tid + i * 512;
        int r = seg >> 3, s = seg & 7;
        cp16(a_base + (uint32_t)(r * 128 + ((s ^ (r & 7)) << 4)),
             ag + (size_t)r * 4096 + s * 16);
    }
    #pragma unroll
    for (int i = 0; i < 2; i++) {                          // B: 1024 x 16B segs
        int seg = tid + i * 512;
        int r = seg >> 3, s = seg & 7;
        cp16(b_base + (uint32_t)(r * 128 + ((s ^ (r & 7)) << 4)),
             bg + (size_t)r * 4096 + s * 16);
    }
    cp_commit();
}

__global__ __launch_bounds__(512, 1)
void gemm_hmma_split(const float* __restrict__ bp, const float* __restrict__ ba)
{
    extern __shared__ char smraw[];
    const uint32_t smem = smem_u32(smraw);

    const int tid = threadIdx.x;
    const int wid = tid >> 5;
    const int lid = tid & 31;
    const int m0  = blockIdx.x * TM;
    const int is_amp = (blockIdx.y >= 8);
    const int n0  = (is_amp ? (int)blockIdx.y - 8 : (int)blockIdx.y) * TN;

    const int wm = (wid & 3) * 32;     // warp m-offset (4x4 warp grid)
    const int wn = (wid >> 2) * 32;    // warp n-offset

    const __half* Apk = g_Xp + (size_t)m0 * KPACK;
    const __half* Bpk = (is_amp ? g_Wa2 : g_Wp2) + (size_t)n0 * KPACK;
    const float* bias = is_amp ? ba : bp;

    // ldmatrix per-lane row/seg components (within x4 group g = lid>>3)
    const int g8 = lid >> 3;
    const int r8 = lid & 7;
    // A: matrices {m0-7/k0-7, m8-15/k0-7, m0-7/k8-15, m8-15/k8-15} = {a0,a1,a2,a3}
    const int aRow = wm + ((g8 & 1) << 3) + r8;
    const int aSeg = (g8 >> 1) << 4;
    // B: matrices {n0-7/k0-7, n0-7/k8-15, n8-15/k0-7, n8-15/k8-15}
    const int bRow = wn + ((g8 >> 1) << 3) + r8;
    const int bSeg = (g8 & 1) << 4;

    float accH[2][4][4], accL[2][4][4];
    #pragma unroll
    for (int mt = 0; mt < 2; mt++)
        #pragma unroll
        for (int nt = 0; nt < 4; nt++)
            #pragma unroll
            for (int i = 0; i < 4; i++) { accH[mt][nt][i] = 0.0f; accL[mt][nt][i] = 0.0f; }

    load_chunk(0, smem, Apk, Bpk, tid);
    load_chunk(1, smem, Apk, Bpk, tid);
    load_chunk(2, smem, Apk, Bpk, tid);
    load_chunk(3, smem, Apk, Bpk, tid);

    for (int c = 0; c < NCHUNK; c++) {
        // Graded drain: pending groups at top of iter c is min(4, NCHUNK-c).
        // wait<k> must have k <= pending-1 so that chunk c itself is complete.
        if      (c <= NCHUNK - 4) cp_wait<3>();
        else if (c == NCHUNK - 3) cp_wait<2>();
        else if (c == NCHUNK - 2) cp_wait<1>();
        else                      cp_wait<0>();
        __syncthreads();
        if (c + 4 < NCHUNK) load_chunk(c + 4, smem, Apk, Bpk, tid);

        const uint32_t aBase = smem + (c % NSTAGE) * STAGE_BYTES;
        const uint32_t bBase = aBase + 16384;

        #pragma unroll
        for (int ks = 0; ks < 2; ks++) {
            const int kbh = ks * 32;        // hi bytes [0,64)
            const int kbl = 64 + ks * 32;   // lo bytes [64,128)

            uint32_t Bh[2][4], Bl[2][4];
            #pragma unroll
            for (int np = 0; np < 2; np++) {
                int row = bRow + np * 16;
                ldsm4(Bh[np][0], Bh[np][1], Bh[np][2], Bh[np][3],
                      bBase + swz(row, kbh + bSeg));
                ldsm4(Bl[np][0], Bl[np][1], Bl[np][2], Bl[np][3],
                      bBase + swz(row, kbl + bSeg));
            }

            #pragma unroll
            for (int mt = 0; mt < 2; mt++) {
                int row = aRow + mt * 16;
                uint32_t Ah[4], Al[4];
                ldsm4(Ah[0], Ah[1], Ah[2], Ah[3], aBase + swz(row, kbh + aSeg));
                ldsm4(Al[0], Al[1], Al[2], Al[3], aBase + swz(row, kbl + aSeg));
                #pragma unroll
                for (int nt = 0; nt < 4; nt++) {
                    const uint32_t* bh = &Bh[nt >> 1][(nt & 1) * 2];
                    const uint32_t* bl = &Bl[nt >> 1][(nt & 1) * 2];
                    mma16816(accH[mt][nt], Ah, bh);   // hi*hi
                    mma16816(accL[mt][nt], Ah, bl);   // hi*lo'
                    mma16816(accL[mt][nt], Al, bh);   // lo'*hi
                }
            }
        }
    }

    // ---- register-direct fused activation epilogue --------------------------
    const float PI_F     = 3.14159265358979f;
    const float STEP     = 1.0471975511965976f;    // pi/3
    const float INV_STEP = 0.9549296585513720f;    // 3/pi
    const float TOL      = 0.15f;

    #pragma unroll
    for (int mt = 0; mt < 2; mt++) {
        #pragma unroll
        for (int nt = 0; nt < 4; nt++) {
            const int col = n0 + wn + nt * 8 + (lid & 3) * 2;
            const float2 bv = *(const float2*)&bias[col];
            #pragma unroll
            for (int h = 0; h < 2; h++) {
                const int m = m0 + wm + mt * 16 + (lid >> 2) + h * 8;
                float z0 = fmaf(accL[mt][nt][h * 2 + 0], LO_UNSCALE,
                                accH[mt][nt][h * 2 + 0]) + bv.x;
                float z1 = fmaf(accL[mt][nt][h * 2 + 1], LO_UNSCALE,
                                accH[mt][nt][h * 2 + 1]) + bv.y;
                if (!is_amp) {
                    float t0 = 1.0f - __fdividef(2.0f, __expf(2.0f * z0) + 1.0f);
                    float t1 = 1.0f - __fdividef(2.0f, __expf(2.0f * z1) + 1.0f);
                    float a0 = t0 * PI_F, a1 = t1 * PI_F;
                    float n0f = rintf(a0 * INV_STEP) * STEP;
                    float n1f = rintf(a1 * INV_STEP) * STEP;
                    a0 = (fabsf(a0 - n0f) < TOL) ? n0f : a0;
                    a1 = (fabsf(a1 - n1f) < TOL) ? n1f : a1;
                    float s0 = __sinf(a0), c0 = __cosf(a0);
                    float s1 = __sinf(a1), c1 = __cosf(a1);
                    float4 w = make_float4(c0 + s0, s0, c1 + s1, s1);
                    *(float4*)&g_cs[(size_t)m * CDIM + col] = w;
                } else {
                    float s0 = __fdividef(1.0f, 1.0f + __expf(-z0));
                    float s1 = __fdividef(1.0f, 1.0f + __expf(-z1));
                    *(float2*)&g_amp[(size_t)m * CDIM + col] = make_float2(s0, s1);
                }
            }
        }
    }
}

// ---------------------------------------------------------------------------
// Sequential scan over T with a per-thread cp.async smem ring.
// Ring = 64 t-slots; chunks of 8 t; 7 chunks (56 steps, >600 cyc) in flight.
// Each thread consumes only slots it wrote itself -> wait_group alone gives
// visibility; no cross-thread sync needed.
// g_cs = (cos+sin, sin)  ->  s' = clip(fma(v.x, s, -v.y), -1, 1)
// ---------------------------------------------------------------------------
#define SRING 64
#define SCHUNK 8
#define SNCH (TSEQ / SCHUNK)   // 256

__global__ __launch_bounds__(64)
void scan_kernel(const float* __restrict__ state_in,
                 float* __restrict__ out,
                 float* __restrict__ state_out)
{
    __shared__ float2 rcs [SRING][64];   // 32 KB
    __shared__ float  ramp[SRING][64];   // 16 KB

    const int tid = threadIdx.x;
    const int idx = blockIdx.x * 64 + tid;   // 0..8191 over (b, c)
    const int b = idx >> 10;
    const int c = idx & (CDIM - 1);

    const float2* __restrict__ pcs = g_cs  + (size_t)b * TSEQ * CDIM + c;
    const float*  __restrict__ pa  = g_amp + (size_t)b * TSEQ * CDIM + c;
    float*        __restrict__ po  = out   + (size_t)b * TSEQ * CDIM + c;

    const uint32_t scs = smem_u32(&rcs[0][tid]);
    const uint32_t sam = smem_u32(&ramp[0][tid]);

    // issue one chunk (8 t-steps) of this thread's chain into the ring
    auto issue = [&](int ch) {
        const int t0 = ch * SCHUNK;
        #pragma unroll
        for (int u = 0; u < SCHUNK; u++) {
            const int t = t0 + u;
            const int sl = t & (SRING - 1);
            cp8(scs + (uint32_t)sl * sizeof(float2) * 64, pcs + (size_t)t * CDIM);
            cp4(sam + (uint32_t)sl * sizeof(float)  * 64, pa  + (size_t)t * CDIM);
        }
        cp_commit();
    };

    #pragma unroll
    for (int ch = 0; ch < 7; ch++) issue(ch);

    float s = state_in[idx];

    // Main loop: steady state has 7 groups pending at the top of each iter.
    for (int ch = 0; ch < SNCH - 7; ch++) {
        cp_wait<6>();          // chunk ch complete
        const int t0 = ch * SCHUNK;
        float2 v[SCHUNK]; float a[SCHUNK];
        #pragma unroll
        for (int u = 0; u < SCHUNK; u++) {
            const int sl = (t0 + u) & (SRING - 1);
            v[u] = rcs[sl][tid];
            a[u] = ramp[sl][tid];
        }
        #pragma unroll
        for (int u = 0; u < SCHUNK; u++) {
            s = fminf(fmaxf(fmaf(v[u].x, s, -v[u].y), -1.0f), 1.0f);
            po[(size_t)(t0 + u) * CDIM] = a[u] * s;
        }
        issue(ch + 7);
    }

    // Drain: wait for ALL remaining groups once, then consume the last 7 chunks.
    cp_wait<0>();
    for (int ch = SNCH - 7; ch < SNCH; ch++) {
        const int t0 = ch * SCHUNK;
        float2 v[SCHUNK]; float a[SCHUNK];
        #pragma unroll
        for (int u = 0; u < SCHUNK; u++) {
            const int sl = (t0 + u) & (SRING - 1);
            v[u] = rcs[sl][tid];
            a[u] = ramp[sl][tid];
        }
        #pragma unroll
        for (int u = 0; u < SCHUNK; u++) {
            s = fminf(fmaxf(fmaf(v[u].x, s, -v[u].y), -1.0f), 1.0f);
            po[(size_t)(t0 + u) * CDIM] = a[u] * s;
        }
    }
    if (state_out) state_out[idx] = s;
}

// ---------------------------------------------------------------------------
extern "C" void kernel_launch(void* const* d_in, const int* in_sizes, int n_in,
                              void* d_out, int out_size)
{
    const float* x  = (const float*)d_in[0];
    const float* st = (const float*)d_in[1];
    const float* Wp = (const float*)d_in[2];
    const float* bp = (const float*)d_in[3];
    const float* Wa = (const float*)d_in[4];
    const float* ba = (const float*)d_in[5];
    float* out = (float*)d_out;

    const size_t BTC = (size_t)MROWS * CDIM;
    float* state_out = ((size_t)out_size >= BTC + (size_t)BBATCH * CDIM)
                       ? out + BTC : nullptr;

    // Unconditional (no static guards): idempotent, not a stream op, capture-safe.
    cudaFuncSetAttribute(gemm_hmma_split,
                         cudaFuncAttributeMaxDynamicSharedMemorySize, SMEM_DYN);

    convert_x<<<8192, 256>>>(x);
    convert_w<<<dim3(512, 2), 256>>>(Wp, Wa);
    gemm_hmma_split<<<dim3(MROWS / TM, 16), 512, SMEM_DYN>>>(bp, ba);
    scan_kernel<<<(BBATCH * CDIM) / 64, 64>>>(st, out, state_out);
}

// round 12
// speedup vs baseline: 3.2887x; 1.1664x over previous
#include <cuda_runtime.h>
#include <cuda_fp16.h>
#include <math.h>
#include <stdint.h>

// ---------------------------------------------------------------------------
// Problem dims (fixed by reference setup_inputs)
// ---------------------------------------------------------------------------
#define BBATCH 8
#define TSEQ   2048
#define CDIM   1024
#define MROWS  (BBATCH * TSEQ)      // 16384
#define KPACK  2048                 // packed per row: 32 chunks x (32 hi | 32 lo) fp16
#define NCHUNK 32                   // 32 chunks of real-K 32

// Exact power-of-2 operand scaling keeps all lo-parts fp16-normal:
//   A (X) scaled by 2^4, B (W) scaled by 2^6 -> every product carries 2^10.
#define A_SCALE  16.0f
#define B_SCALE  64.0f
#define Z_UNSCALE 9.765625e-4f      // 2^-10, exact

// GEMM tile: CTA 128x128, 8 warps of 64x32, 256 threads, 2 CTAs/SM
#define TM 128
#define TN 128
#define STAGE_BYTES 32768           // A tile 16KB + B tile 16KB
#define NSTAGE 3
#define SMEM_DYN (NSTAGE * STAGE_BYTES)   // 96 KB

// ---------------------------------------------------------------------------
// Device scratch (no runtime allocation allowed)
// ---------------------------------------------------------------------------
__device__ __half g_Xp [(size_t)MROWS * KPACK];   // 64 MB packed X*16 (hi|lo)
__device__ __half g_Wp2[(size_t)CDIM * KPACK];    // 4 MB packed W_phi*64
__device__ __half g_Wa2[(size_t)CDIM * KPACK];    // 4 MB packed W_amp*64
__device__ float2 g_cs [(size_t)MROWS * CDIM];    // (cos+sin, sin)
__device__ float  g_amp[(size_t)MROWS * CDIM];

// ---------------------------------------------------------------------------
// PTX helpers (sm_80-era instructions only: valid on compute_100 target)
// ---------------------------------------------------------------------------
__device__ __forceinline__ uint32_t smem_u32(const void* p) {
    uint32_t a;
    asm("{ .reg .u64 t; cvta.to.shared.u64 t, %1; cvt.u32.u64 %0, t; }"
        : "=r"(a) : "l"(p));
    return a;
}
__device__ __forceinline__ void cp16(uint32_t dst, const void* src) {
    asm volatile("cp.async.cg.shared.global [%0], [%1], 16;" :: "r"(dst), "l"(src));
}
__device__ __forceinline__ void cp8(uint32_t dst, const void* src) {
    asm volatile("cp.async.ca.shared.global [%0], [%1], 8;" :: "r"(dst), "l"(src));
}
__device__ __forceinline__ void cp4(uint32_t dst, const void* src) {
    asm volatile("cp.async.ca.shared.global [%0], [%1], 4;" :: "r"(dst), "l"(src));
}
__device__ __forceinline__ void cp_commit() {
    asm volatile("cp.async.commit_group;" ::: "memory");
}
template<int N> __device__ __forceinline__ void cp_wait() {
    asm volatile("cp.async.wait_group %0;" :: "n"(N) : "memory");
}
__device__ __forceinline__ void ldsm4(uint32_t& r0, uint32_t& r1,
                                      uint32_t& r2, uint32_t& r3, uint32_t addr) {
    asm volatile("ldmatrix.sync.aligned.m8n8.x4.shared.b16 {%0,%1,%2,%3}, [%4];"
                 : "=r"(r0), "=r"(r1), "=r"(r2), "=r"(r3) : "r"(addr));
}
__device__ __forceinline__ void mma16816(float* c, const uint32_t* a, const uint32_t* b) {
    asm volatile("mma.sync.aligned.m16n8k16.row.col.f32.f16.f16.f32 "
                 "{%0,%1,%2,%3}, {%4,%5,%6,%7}, {%8,%9}, {%0,%1,%2,%3};"
                 : "+f"(c[0]), "+f"(c[1]), "+f"(c[2]), "+f"(c[3])
                 : "r"(a[0]), "r"(a[1]), "r"(a[2]), "r"(a[3]),
                   "r"(b[0]), "r"(b[1]));
}
// swizzled smem offset within a [row][128B] tile (SW128-style: seg ^ (row&7))
__device__ __forceinline__ uint32_t swz(int row, int byteoff) {
    return (uint32_t)(row * 128 + ((((byteoff >> 4) ^ (row & 7)) << 4) | (byteoff & 15)));
}

// ---------------------------------------------------------------------------
// Conversion kernels: fp32 -> packed fp16 (hi | lo per 32-K chunk), pre-scaled
// ---------------------------------------------------------------------------
__global__ __launch_bounds__(256)
void convert_x(const float* __restrict__ x)
{
    int g  = blockIdx.x * 256 + threadIdx.x;
    int m  = g >> 7;
    int k0 = (g & 127) << 3;
    const float* src = x + (size_t)m * CDIM + k0;
    float4 v0 = *(const float4*)(src);
    float4 v1 = *(const float4*)(src + 4);
    float f[8] = {v0.x, v0.y, v0.z, v0.w, v1.x, v1.y, v1.z, v1.w};
    __align__(16) __half h[8];
    __align__(16) __half l[8];
    #pragma unroll
    for (int i = 0; i < 8; i++) {
        float fs = f[i] * A_SCALE;          // exact
        h[i] = __float2half_rn(fs);
        l[i] = __float2half_rn(fs - __half2float(h[i]));
    }
    size_t base = (size_t)m * KPACK + (size_t)((k0 >> 5) << 6) + (k0 & 31);
    *(uint4*)&g_Xp[base]      = *(uint4*)h;
    *(uint4*)&g_Xp[base + 32] = *(uint4*)l;
}

__global__ __launch_bounds__(256)
void convert_w(const float* __restrict__ Wp, const float* __restrict__ Wa)
{
    const float* W = blockIdx.y ? Wa : Wp;
    __half* D = blockIdx.y ? g_Wa2 : g_Wp2;
    int g  = blockIdx.x * 256 + threadIdx.x;
    int n  = g >> 7;
    int k0 = (g & 127) << 3;
    const float* src = W + (size_t)n * CDIM + k0;
    float4 v0 = *(const float4*)(src);
    float4 v1 = *(const float4*)(src + 4);
    float f[8] = {v0.x, v0.y, v0.z, v0.w, v1.x, v1.y, v1.z, v1.w};
    __align__(16) __half h[8];
    __align__(16) __half l[8];
    #pragma unroll
    for (int i = 0; i < 8; i++) {
        float fs = f[i] * B_SCALE;          // exact
        h[i] = __float2half_rn(fs);
        l[i] = __float2half_rn(fs - __half2float(h[i]));
    }
    size_t base = (size_t)n * KPACK + (size_t)((k0 >> 5) << 6) + (k0 & 31);
    *(uint4*)&D[base]      = *(uint4*)h;
    *(uint4*)&D[base + 32] = *(uint4*)l;
}

// ---------------------------------------------------------------------------
// fp16 3-term split GEMM via mma.sync (HMMA), single merged fp32 accumulator:
//   acc = Ah*Bh + Ah*Bl + Al*Bh    (all terms carry the exact 2^10 scale)
//   z   = acc * 2^-10 + bias
// grid = (128, 16): y<8 -> phi tile (n0 = y*128), y>=8 -> amp (n0 = (y-8)*128)
// ---------------------------------------------------------------------------
__device__ __forceinline__ void load_chunk(int c, uint32_t smem,
                                           const __half* Apk,
                                           const __half* Bpk,
                                           int tid)
{
    const uint32_t a_base = smem + (c % NSTAGE) * STAGE_BYTES;
    const uint32_t b_base = a_base + 16384;
    const char* ag = (const char*)Apk + (size_t)c * 128;   // row stride 4096B
    const char* bg = (const char*)Bpk + (size_t)c * 128;
    #pragma unroll
    for (int i = 0; i < 4; i++) {                          // A: 1024 x 16B segs
        int seg = tid + i * 256;
        int r = seg >> 3, s = seg & 7;
        cp16(a_base + (uint32_t)(r * 128 + ((s ^ (r & 7)) << 4)),
             ag + (size_t)r * 4096 + s * 16);
    }
    #pragma unroll
    for (int i = 0; i < 4; i++) {                          // B: 1024 x 16B segs
        int seg = tid + i * 256;
        int r = seg >> 3, s = seg & 7;
        cp16(b_base + (uint32_t)(r * 128 + ((s ^ (r & 7)) << 4)),
             bg + (size_t)r * 4096 + s * 16);
    }
    cp_commit();
}

__global__ __launch_bounds__(256, 2)
void gemm_hmma_split(const float* __restrict__ bp, const float* __restrict__ ba)
{
    extern __shared__ char smraw[];
    const uint32_t smem = smem_u32(smraw);

    const int tid = threadIdx.x;
    const int wid = tid >> 5;
    const int lid = tid & 31;
    const int m0  = blockIdx.x * TM;
    const int is_amp = (blockIdx.y >= 8);
    const int n0  = (is_amp ? (int)blockIdx.y - 8 : (int)blockIdx.y) * TN;

    const int wm = (wid & 1) * 64;     // warp m-offset (2x4 warp grid)
    const int wn = (wid >> 1) * 32;    // warp n-offset

    const __half* Apk = g_Xp + (size_t)m0 * KPACK;
    const __half* Bpk = (is_amp ? g_Wa2 : g_Wp2) + (size_t)n0 * KPACK;
    const float* bias = is_amp ? ba : bp;

    // ldmatrix per-lane row/seg components (within x4 group g = lid>>3)
    const int g8 = lid >> 3;
    const int r8 = lid & 7;
    // A: matrices {m0-7/k0-7, m8-15/k0-7, m0-7/k8-15, m8-15/k8-15} = {a0,a1,a2,a3}
    const int aRow = wm + ((g8 & 1) << 3) + r8;
    const int aSeg = (g8 >> 1) << 4;
    // B: matrices {n0-7/k0-7, n0-7/k8-15, n8-15/k0-7, n8-15/k8-15}
    const int bRow = wn + ((g8 >> 1) << 3) + r8;
    const int bSeg = (g8 & 1) << 4;

    float acc[4][4][4];
    #pragma unroll
    for (int mt = 0; mt < 4; mt++)
        #pragma unroll
        for (int nt = 0; nt < 4; nt++)
            #pragma unroll
            for (int i = 0; i < 4; i++) acc[mt][nt][i] = 0.0f;

    load_chunk(0, smem, Apk, Bpk, tid);
    load_chunk(1, smem, Apk, Bpk, tid);

    for (int c = 0; c < NCHUNK; c++) {
        if (c < NCHUNK - 1) cp_wait<1>(); else cp_wait<0>();
        __syncthreads();
        if (c + 2 < NCHUNK) load_chunk(c + 2, smem, Apk, Bpk, tid);

        const uint32_t aBase = smem + (c % NSTAGE) * STAGE_BYTES;
        const uint32_t bBase = aBase + 16384;

        #pragma unroll
        for (int ks = 0; ks < 2; ks++) {
            const int kbh = ks * 32;        // hi bytes [0,64)
            const int kbl = 64 + ks * 32;   // lo bytes [64,128)

            uint32_t Bh[2][4], Bl[2][4];
            #pragma unroll
            for (int np = 0; np < 2; np++) {
                int row = bRow + np * 16;
                ldsm4(Bh[np][0], Bh[np][1], Bh[np][2], Bh[np][3],
                      bBase + swz(row, kbh + bSeg));
                ldsm4(Bl[np][0], Bl[np][1], Bl[np][2], Bl[np][3],
                      bBase + swz(row, kbl + bSeg));
            }

            #pragma unroll
            for (int mt = 0; mt < 4; mt++) {
                int row = aRow + mt * 16;
                uint32_t Ah[4], Al[4];
                ldsm4(Ah[0], Ah[1], Ah[2], Ah[3], aBase + swz(row, kbh + aSeg));
                ldsm4(Al[0], Al[1], Al[2], Al[3], aBase + swz(row, kbl + aSeg));
                #pragma unroll
                for (int nt = 0; nt < 4; nt++) {
                    const uint32_t* bh = &Bh[nt >> 1][(nt & 1) * 2];
                    const uint32_t* bl = &Bl[nt >> 1][(nt & 1) * 2];
                    mma16816(acc[mt][nt], Ah, bh);   // hi*hi
                    mma16816(acc[mt][nt], Ah, bl);   // hi*lo
                    mma16816(acc[mt][nt], Al, bh);   // lo*hi
                }
            }
        }
    }

    // ---- register-direct fused activation epilogue --------------------------
    const float PI_F     = 3.14159265358979f;
    const float STEP     = 1.0471975511965976f;    // pi/3
    const float INV_STEP = 0.9549296585513720f;    // 3/pi
    const float TOL      = 0.15f;

    #pragma unroll
    for (int mt = 0; mt < 4; mt++) {
        #pragma unroll
        for (int nt = 0; nt < 4; nt++) {
            const int col = n0 + wn + nt * 8 + (lid & 3) * 2;
            const float2 bv = *(const float2*)&bias[col];
            #pragma unroll
            for (int h = 0; h < 2; h++) {
                const int m = m0 + wm + mt * 16 + (lid >> 2) + h * 8;
                float z0 = fmaf(acc[mt][nt][h * 2 + 0], Z_UNSCALE, bv.x);
                float z1 = fmaf(acc[mt][nt][h * 2 + 1], Z_UNSCALE, bv.y);
                if (!is_amp) {
                    float t0 = 1.0f - __fdividef(2.0f, __expf(2.0f * z0) + 1.0f);
                    float t1 = 1.0f - __fdividef(2.0f, __expf(2.0f * z1) + 1.0f);
                    float a0 = t0 * PI_F, a1 = t1 * PI_F;
                    float n0f = rintf(a0 * INV_STEP) * STEP;
                    float n1f = rintf(a1 * INV_STEP) * STEP;
                    a0 = (fabsf(a0 - n0f) < TOL) ? n0f : a0;
                    a1 = (fabsf(a1 - n1f) < TOL) ? n1f : a1;
                    float s0 = __sinf(a0), c0 = __cosf(a0);
                    float s1 = __sinf(a1), c1 = __cosf(a1);
                    float4 w = make_float4(c0 + s0, s0, c1 + s1, s1);
                    *(float4*)&g_cs[(size_t)m * CDIM + col] = w;
                } else {
                    float s0 = __fdividef(1.0f, 1.0f + __expf(-z0));
                    float s1 = __fdividef(1.0f, 1.0f + __expf(-z1));
                    *(float2*)&g_amp[(size_t)m * CDIM + col] = make_float2(s0, s1);
                }
            }
        }
    }
}

// ---------------------------------------------------------------------------
// Sequential scan over T with a per-thread cp.async smem ring (measured 53.7us).
// Ring = 64 t-slots; chunks of 8 t; 7 chunks in flight; graded drain at end.
// g_cs = (cos+sin, sin)  ->  s' = clip(fma(v.x, s, -v.y), -1, 1)
// ---------------------------------------------------------------------------
#define SRING 64
#define SCHUNK 8
#define SNCH (TSEQ / SCHUNK)   // 256

__global__ __launch_bounds__(64)
void scan_kernel(const float* __restrict__ state_in,
                 float* __restrict__ out,
                 float* __restrict__ state_out)
{
    __shared__ float2 rcs [SRING][64];   // 32 KB
    __shared__ float  ramp[SRING][64];   // 16 KB

    const int tid = threadIdx.x;
    const int idx = blockIdx.x * 64 + tid;   // 0..8191 over (b, c)
    const int b = idx >> 10;
    const int c = idx & (CDIM - 1);

    const float2* __restrict__ pcs = g_cs  + (size_t)b * TSEQ * CDIM + c;
    const float*  __restrict__ pa  = g_amp + (size_t)b * TSEQ * CDIM + c;
    float*        __restrict__ po  = out   + (size_t)b * TSEQ * CDIM + c;

    const uint32_t scs = smem_u32(&rcs[0][tid]);
    const uint32_t sam = smem_u32(&ramp[0][tid]);

    // issue one chunk (8 t-steps) of this thread's chain into the ring
    auto issue = [&](int ch) {
        const int t0 = ch * SCHUNK;
        #pragma unroll
        for (int u = 0; u < SCHUNK; u++) {
            const int t = t0 + u;
            const int sl = t & (SRING - 1);
            cp8(scs + (uint32_t)sl * sizeof(float2) * 64, pcs + (size_t)t * CDIM);
            cp4(sam + (uint32_t)sl * sizeof(float)  * 64, pa  + (size_t)t * CDIM);
        }
        cp_commit();
    };

    #pragma unroll
    for (int ch = 0; ch < 7; ch++) issue(ch);

    float s = state_in[idx];

    // Main loop: steady state has 7 groups pending at the top of each iter.
    for (int ch = 0; ch < SNCH - 7; ch++) {
        cp_wait<6>();          // chunk ch complete
        const int t0 = ch * SCHUNK;
        float2 v[SCHUNK]; float a[SCHUNK];
        #pragma unroll
        for (int u = 0; u < SCHUNK; u++) {
            const int sl = (t0 + u) & (SRING - 1);
            v[u] = rcs[sl][tid];
            a[u] = ramp[sl][tid];
        }
        #pragma unroll
        for (int u = 0; u < SCHUNK; u++) {
            s = fminf(fmaxf(fmaf(v[u].x, s, -v[u].y), -1.0f), 1.0f);
            po[(size_t)(t0 + u) * CDIM] = a[u] * s;
        }
        issue(ch + 7);
    }

    // Drain: wait for ALL remaining groups once, then consume the last 7 chunks.
    cp_wait<0>();
    for (int ch = SNCH - 7; ch < SNCH; ch++) {
        const int t0 = ch * SCHUNK;
        float2 v[SCHUNK]; float a[SCHUNK];
        #pragma unroll
        for (int u = 0; u < SCHUNK; u++) {
            const int sl = (t0 + u) & (SRING - 1);
            v[u] = rcs[sl][tid];
            a[u] = ramp[sl][tid];
        }
        #pragma unroll
        for (int u = 0; u < SCHUNK; u++) {
            s = fminf(fmaxf(fmaf(v[u].x, s, -v[u].y), -1.0f), 1.0f);
            po[(size_t)(t0 + u) * CDIM] = a[u] * s;
        }
    }
    if (state_out) state_out[idx] = s;
}

// ---------------------------------------------------------------------------
extern "C" void kernel_launch(void* const* d_in, const int* in_sizes, int n_in,
                              void* d_out, int out_size)
{
    const float* x  = (const float*)d_in[0];
    const float* st = (const float*)d_in[1];
    const float* Wp = (const float*)d_in[2];
    const float* bp = (const float*)d_in[3];
    const float* Wa = (const float*)d_in[4];
    const float* ba = (const float*)d_in[5];
    float* out = (float*)d_out;

    const size_t BTC = (size_t)MROWS * CDIM;
    float* state_out = ((size_t)out_size >= BTC + (size_t)BBATCH * CDIM)
                       ? out + BTC : nullptr;

    // Unconditional (no static guards): idempotent, not a stream op, capture-safe.
    cudaFuncSetAttribute(gemm_hmma_split,
                         cudaFuncAttributeMaxDynamicSharedMemorySize, SMEM_DYN);

    convert_x<<<8192, 256>>>(x);
    convert_w<<<dim3(512, 2), 256>>>(Wp, Wa);
    gemm_hmma_split<<<dim3(MROWS / TM, 16), 256, SMEM_DYN>>>(bp, ba);
    scan_kernel<<<(BBATCH * CDIM) / 64, 64>>>(st, out, state_out);
}

// round 15
// speedup vs baseline: 3.3766x; 1.0267x over previous
#include <cuda_runtime.h>
#include <cuda_fp16.h>
#include <math.h>
#include <stdint.h>

// ---------------------------------------------------------------------------
// Problem dims (fixed by reference setup_inputs)
// ---------------------------------------------------------------------------
#define BBATCH 8
#define TSEQ   2048
#define CDIM   1024
#define MROWS  (BBATCH * TSEQ)      // 16384
#define KPACK  2048                 // packed per row: 32 chunks x (32 hi | 32 lo) fp16
#define NCHUNK 32                   // 32 chunks of real-K 32

// Exact power-of-2 operand scaling keeps all lo-parts fp16-normal:
//   A (X) scaled by 2^4, B (W) scaled by 2^6 -> every product carries 2^10.
#define A_SCALE  16.0f
#define B_SCALE  64.0f
#define Z_UNSCALE 9.765625e-4f      // 2^-10, exact

// GEMM tile: CTA 128x128, 4 warps of 64x64, 128 threads, 2 CTAs/SM
#define TM 128
#define TN 128
#define STAGE_BYTES 32768           // A tile 16KB + B tile 16KB
#define NSTAGE 3
#define SMEM_DYN (NSTAGE * STAGE_BYTES)   // 96 KB

// ---------------------------------------------------------------------------
// Device scratch (no runtime allocation allowed)
// ---------------------------------------------------------------------------
__device__ __half g_Xp [(size_t)MROWS * KPACK];   // 64 MB packed X*16 (hi|lo)
__device__ __half g_Wp2[(size_t)CDIM * KPACK];    // 4 MB packed W_phi*64
__device__ __half g_Wa2[(size_t)CDIM * KPACK];    // 4 MB packed W_amp*64
__device__ float2 g_cs [(size_t)MROWS * CDIM];    // (cos+sin, sin)
__device__ float  g_amp[(size_t)MROWS * CDIM];

// ---------------------------------------------------------------------------
// PTX helpers (sm_80-era instructions only: valid on compute_100 target)
// ---------------------------------------------------------------------------
__device__ __forceinline__ uint32_t smem_u32(const void* p) {
    uint32_t a;
    asm("{ .reg .u64 t; cvta.to.shared.u64 t, %1; cvt.u32.u64 %0, t; }"
        : "=r"(a) : "l"(p));
    return a;
}
__device__ __forceinline__ void cp16(uint32_t dst, const void* src) {
    asm volatile("cp.async.cg.shared.global [%0], [%1], 16;" :: "r"(dst), "l"(src));
}
__device__ __forceinline__ void cp8(uint32_t dst, const void* src) {
    asm volatile("cp.async.ca.shared.global [%0], [%1], 8;" :: "r"(dst), "l"(src));
}
__device__ __forceinline__ void cp4(uint32_t dst, const void* src) {
    asm volatile("cp.async.ca.shared.global [%0], [%1], 4;" :: "r"(dst), "l"(src));
}
__device__ __forceinline__ void cp_commit() {
    asm volatile("cp.async.commit_group;" ::: "memory");
}
template<int N> __device__ __forceinline__ void cp_wait() {
    asm volatile("cp.async.wait_group %0;" :: "n"(N) : "memory");
}
__device__ __forceinline__ void ldsm4(uint32_t& r0, uint32_t& r1,
                                      uint32_t& r2, uint32_t& r3, uint32_t addr) {
    asm volatile("ldmatrix.sync.aligned.m8n8.x4.shared.b16 {%0,%1,%2,%3}, [%4];"
                 : "=r"(r0), "=r"(r1), "=r"(r2), "=r"(r3) : "r"(addr));
}
__device__ __forceinline__ void mma16816(float* c, const uint32_t* a, const uint32_t* b) {
    asm volatile("mma.sync.aligned.m16n8k16.row.col.f32.f16.f16.f32 "
                 "{%0,%1,%2,%3}, {%4,%5,%6,%7}, {%8,%9}, {%0,%1,%2,%3};"
                 : "+f"(c[0]), "+f"(c[1]), "+f"(c[2]), "+f"(c[3])
                 : "r"(a[0]), "r"(a[1]), "r"(a[2]), "r"(a[3]),
                   "r"(b[0]), "r"(b[1]));
}
// swizzled smem offset within a [row][128B] tile (SW128-style: seg ^ (row&7))
__device__ __forceinline__ uint32_t swz(int row, int byteoff) {
    return (uint32_t)(row * 128 + ((((byteoff >> 4) ^ (row & 7)) << 4) | (byteoff & 15)));
}

// ---------------------------------------------------------------------------
// Conversion kernels: fp32 -> packed fp16 (hi | lo per 32-K chunk), pre-scaled
// ---------------------------------------------------------------------------
__global__ __launch_bounds__(256)
void convert_x(const float* __restrict__ x)
{
    int g  = blockIdx.x * 256 + threadIdx.x;
    int m  = g >> 7;
    int k0 = (g & 127) << 3;
    const float* src = x + (size_t)m * CDIM + k0;
    float4 v0 = *(const float4*)(src);
    float4 v1 = *(const float4*)(src + 4);
    float f[8] = {v0.x, v0.y, v0.z, v0.w, v1.x, v1.y, v1.z, v1.w};
    __align__(16) __half h[8];
    __align__(16) __half l[8];
    #pragma unroll
    for (int i = 0; i < 8; i++) {
        float fs = f[i] * A_SCALE;          // exact
        h[i] = __float2half_rn(fs);
        l[i] = __float2half_rn(fs - __half2float(h[i]));
    }
    size_t base = (size_t)m * KPACK + (size_t)((k0 >> 5) << 6) + (k0 & 31);
    *(uint4*)&g_Xp[base]      = *(uint4*)h;
    *(uint4*)&g_Xp[base + 32] = *(uint4*)l;
}

__global__ __launch_bounds__(256)
void convert_w(const float* __restrict__ Wp, const float* __restrict__ Wa)
{
    const float* W = blockIdx.y ? Wa : Wp;
    __half* D = blockIdx.y ? g_Wa2 : g_Wp2;
    int g  = blockIdx.x * 256 + threadIdx.x;
    int n  = g >> 7;
    int k0 = (g & 127) << 3;
    const float* src = W + (size_t)n * CDIM + k0;
    float4 v0 = *(const float4*)(src);
    float4 v1 = *(const float4*)(src + 4);
    float f[8] = {v0.x, v0.y, v0.z, v0.w, v1.x, v1.y, v1.z, v1.w};
    __align__(16) __half h[8];
    __align__(16) __half l[8];
    #pragma unroll
    for (int i = 0; i < 8; i++) {
        float fs = f[i] * B_SCALE;          // exact
        h[i] = __float2half_rn(fs);
        l[i] = __float2half_rn(fs - __half2float(h[i]));
    }
    size_t base = (size_t)n * KPACK + (size_t)((k0 >> 5) << 6) + (k0 & 31);
    *(uint4*)&D[base]      = *(uint4*)h;
    *(uint4*)&D[base + 32] = *(uint4*)l;
}

// ---------------------------------------------------------------------------
// fp16 3-term split GEMM via mma.sync (HMMA), single merged fp32 accumulator:
//   acc = Ah*Bh + Ah*Bl + Al*Bh    (all terms carry the exact 2^10 scale)
//   z   = acc * 2^-10 + bias
// 4 warps of 64x64 -> smem read traffic 64KB/chunk/CTA (was 96KB with 64x32).
// grid = (128, 16): y<8 -> phi tile (n0 = y*128), y>=8 -> amp (n0 = (y-8)*128)
// ---------------------------------------------------------------------------
__device__ __forceinline__ void load_chunk(int c, uint32_t smem,
                                           const __half* Apk,
                                           const __half* Bpk,
                                           int tid)
{
    const uint32_t a_base = smem + (c % NSTAGE) * STAGE_BYTES;
    const uint32_t b_base = a_base + 16384;
    const char* ag = (const char*)Apk + (size_t)c * 128;   // row stride 4096B
    const char* bg = (const char*)Bpk + (size_t)c * 128;
    #pragma unroll
    for (int i = 0; i < 8; i++) {                          // A: 1024 x 16B segs / 128 thr
        int seg = tid + i * 128;
        int r = seg >> 3, s = seg & 7;
        cp16(a_base + (uint32_t)(r * 128 + ((s ^ (r & 7)) << 4)),
             ag + (size_t)r * 4096 + s * 16);
    }
    #pragma unroll
    for (int i = 0; i < 8; i++) {                          // B: 1024 x 16B segs
        int seg = tid + i * 128;
        int r = seg >> 3, s = seg & 7;
        cp16(b_base + (uint32_t)(r * 128 + ((s ^ (r & 7)) << 4)),
             bg + (size_t)r * 4096 + s * 16);
    }
    cp_commit();
}

__global__ __launch_bounds__(128, 2)
void gemm_hmma_split(const float* __restrict__ bp, const float* __restrict__ ba)
{
    extern __shared__ char smraw[];
    const uint32_t smem = smem_u32(smraw);

    const int tid = threadIdx.x;
    const int wid = tid >> 5;
    const int lid = tid & 31;
    const int m0  = blockIdx.x * TM;
    const int is_amp = (blockIdx.y >= 8);
    const int n0  = (is_amp ? (int)blockIdx.y - 8 : (int)blockIdx.y) * TN;

    const int wm = (wid & 1) * 64;     // warp m-offset (2x2 warp grid)
    const int wn = (wid >> 1) * 64;    // warp n-offset

    const __half* Apk = g_Xp + (size_t)m0 * KPACK;
    const __half* Bpk = (is_amp ? g_Wa2 : g_Wp2) + (size_t)n0 * KPACK;
    const float* bias = is_amp ? ba : bp;

    // ldmatrix per-lane row/seg components (within x4 group g = lid>>3)
    const int g8 = lid >> 3;
    const int r8 = lid & 7;
    // A: matrices {m0-7/k0-7, m8-15/k0-7, m0-7/k8-15, m8-15/k8-15} = {a0,a1,a2,a3}
    const int aRow = wm + ((g8 & 1) << 3) + r8;
    const int aSeg = (g8 >> 1) << 4;
    // B: matrices {n0-7/k0-7, n0-7/k8-15, n8-15/k0-7, n8-15/k8-15}
    const int bRow = wn + ((g8 >> 1) << 3) + r8;
    const int bSeg = (g8 & 1) << 4;

    float acc[4][8][4];
    #pragma unroll
    for (int mt = 0; mt < 4; mt++)
        #pragma unroll
        for (int nt = 0; nt < 8; nt++)
            #pragma unroll
            for (int i = 0; i < 4; i++) acc[mt][nt][i] = 0.0f;

    load_chunk(0, smem, Apk, Bpk, tid);
    load_chunk(1, smem, Apk, Bpk, tid);

    for (int c = 0; c < NCHUNK; c++) {
        if (c < NCHUNK - 1) cp_wait<1>(); else cp_wait<0>();
        __syncthreads();
        if (c + 2 < NCHUNK) load_chunk(c + 2, smem, Apk, Bpk, tid);

        const uint32_t aBase = smem + (c % NSTAGE) * STAGE_BYTES;
        const uint32_t bBase = aBase + 16384;

        #pragma unroll
        for (int ks = 0; ks < 2; ks++) {
            const int kbh = ks * 32;        // hi bytes [0,64)
            const int kbl = 64 + ks * 32;   // lo bytes [64,128)

            uint32_t Bh[4][4], Bl[4][4];    // 4 x n16 groups (64 cols)
            #pragma unroll
            for (int np = 0; np < 4; np++) {
                int row = bRow + np * 16;
                ldsm4(Bh[np][0], Bh[np][1], Bh[np][2], Bh[np][3],
                      bBase + swz(row, kbh + bSeg));
                ldsm4(Bl[np][0], Bl[np][1], Bl[np][2], Bl[np][3],
                      bBase + swz(row, kbl + bSeg));
            }

            #pragma unroll
            for (int mt = 0; mt < 4; mt++) {
                int row = aRow + mt * 16;
                uint32_t Ah[4], Al[4];
                ldsm4(Ah[0], Ah[1], Ah[2], Ah[3], aBase + swz(row, kbh + aSeg));
                ldsm4(Al[0], Al[1], Al[2], Al[3], aBase + swz(row, kbl + aSeg));
                #pragma unroll
                for (int nt = 0; nt < 8; nt++) {
                    const uint32_t* bh = &Bh[nt >> 1][(nt & 1) * 2];
                    const uint32_t* bl = &Bl[nt >> 1][(nt & 1) * 2];
                    mma16816(acc[mt][nt], Ah, bh);   // hi*hi
                    mma16816(acc[mt][nt], Ah, bl);   // hi*lo
                    mma16816(acc[mt][nt], Al, bh);   // lo*hi
                }
            }
        }
    }

    // ---- register-direct fused activation epilogue --------------------------
    const float PI_F     = 3.14159265358979f;
    const float STEP     = 1.0471975511965976f;    // pi/3
    const float INV_STEP = 0.9549296585513720f;    // 3/pi
    const float TOL      = 0.15f;

    #pragma unroll
    for (int mt = 0; mt < 4; mt++) {
        #pragma unroll
        for (int nt = 0; nt < 8; nt++) {
            const int col = n0 + wn + nt * 8 + (lid & 3) * 2;
            const float2 bv = *(const float2*)&bias[col];
            #pragma unroll
            for (int h = 0; h < 2; h++) {
                const int m = m0 + wm + mt * 16 + (lid >> 2) + h * 8;
                float z0 = fmaf(acc[mt][nt][h * 2 + 0], Z_UNSCALE, bv.x);
                float z1 = fmaf(acc[mt][nt][h * 2 + 1], Z_UNSCALE, bv.y);
                if (!is_amp) {
                    float t0 = 1.0f - __fdividef(2.0f, __expf(2.0f * z0) + 1.0f);
                    float t1 = 1.0f - __fdividef(2.0f, __expf(2.0f * z1) + 1.0f);
                    float a0 = t0 * PI_F, a1 = t1 * PI_F;
                    float n0f = rintf(a0 * INV_STEP) * STEP;
                    float n1f = rintf(a1 * INV_STEP) * STEP;
                    a0 = (fabsf(a0 - n0f) < TOL) ? n0f : a0;
                    a1 = (fabsf(a1 - n1f) < TOL) ? n1f : a1;
                    float s0 = __sinf(a0), c0 = __cosf(a0);
                    float s1 = __sinf(a1), c1 = __cosf(a1);
                    float4 w = make_float4(c0 + s0, s0, c1 + s1, s1);
                    *(float4*)&g_cs[(size_t)m * CDIM + col] = w;
                } else {
                    float s0 = __fdividef(1.0f, 1.0f + __expf(-z0));
                    float s1 = __fdividef(1.0f, 1.0f + __expf(-z1));
                    *(float2*)&g_amp[(size_t)m * CDIM + col] = make_float2(s0, s1);
                }
            }
        }
    }
}

// ---------------------------------------------------------------------------
// Sequential scan over T with a per-thread cp.async smem ring (measured 53.7us).
// Ring = 64 t-slots; chunks of 8 t; 7 chunks in flight; graded drain at end.
// g_cs = (cos+sin, sin)  ->  s' = clip(fma(v.x, s, -v.y), -1, 1)
// ---------------------------------------------------------------------------
#define SRING 64
#define SCHUNK 8
#define SNCH (TSEQ / SCHUNK)   // 256

__global__ __launch_bounds__(64)
void scan_kernel(const float* __restrict__ state_in,
                 float* __restrict__ out,
                 float* __restrict__ state_out)
{
    __shared__ float2 rcs [SRING][64];   // 32 KB
    __shared__ float  ramp[SRING][64];   // 16 KB

    const int tid = threadIdx.x;
    const int idx = blockIdx.x * 64 + tid;   // 0..8191 over (b, c)
    const int b = idx >> 10;
    const int c = idx & (CDIM - 1);

    const float2* __restrict__ pcs = g_cs  + (size_t)b * TSEQ * CDIM + c;
    const float*  __restrict__ pa  = g_amp + (size_t)b * TSEQ * CDIM + c;
    float*        __restrict__ po  = out   + (size_t)b * TSEQ * CDIM + c;

    const uint32_t scs = smem_u32(&rcs[0][tid]);
    const uint32_t sam = smem_u32(&ramp[0][tid]);

    // issue one chunk (8 t-steps) of this thread's chain into the ring
    auto issue = [&](int ch) {
        const int t0 = ch * SCHUNK;
        #pragma unroll
        for (int u = 0; u < SCHUNK; u++) {
            const int t = t0 + u;
            const int sl = t & (SRING - 1);
            cp8(scs + (uint32_t)sl * sizeof(float2) * 64, pcs + (size_t)t * CDIM);
            cp4(sam + (uint32_t)sl * sizeof(float)  * 64, pa  + (size_t)t * CDIM);
        }
        cp_commit();
    };

    #pragma unroll
    for (int ch = 0; ch < 7; ch++) issue(ch);

    float s = state_in[idx];

    // Main loop: steady state has 7 groups pending at the top of each iter.
    for (int ch = 0; ch < SNCH - 7; ch++) {
        cp_wait<6>();          // chunk ch complete
        const int t0 = ch * SCHUNK;
        float2 v[SCHUNK]; float a[SCHUNK];
        #pragma unroll
        for (int u = 0; u < SCHUNK; u++) {
            const int sl = (t0 + u) & (SRING - 1);
            v[u] = rcs[sl][tid];
            a[u] = ramp[sl][tid];
        }
        #pragma unroll
        for (int u = 0; u < SCHUNK; u++) {
            s = fminf(fmaxf(fmaf(v[u].x, s, -v[u].y), -1.0f), 1.0f);
            po[(size_t)(t0 + u) * CDIM] = a[u] * s;
        }
        issue(ch + 7);
    }

    // Drain: wait for ALL remaining groups once, then consume the last 7 chunks.
    cp_wait<0>();
    for (int ch = SNCH - 7; ch < SNCH; ch++) {
        const int t0 = ch * SCHUNK;
        float2 v[SCHUNK]; float a[SCHUNK];
        #pragma unroll
        for (int u = 0; u < SCHUNK; u++) {
            const int sl = (t0 + u) & (SRING - 1);
            v[u] = rcs[sl][tid];
            a[u] = ramp[sl][tid];
        }
        #pragma unroll
        for (int u = 0; u < SCHUNK; u++) {
            s = fminf(fmaxf(fmaf(v[u].x, s, -v[u].y), -1.0f), 1.0f);
            po[(size_t)(t0 + u) * CDIM] = a[u] * s;
        }
    }
    if (state_out) state_out[idx] = s;
}

// ---------------------------------------------------------------------------
extern "C" void kernel_launch(void* const* d_in, const int* in_sizes, int n_in,
                              void* d_out, int out_size)
{
    const float* x  = (const float*)d_in[0];
    const float* st = (const float*)d_in[1];
    const float* Wp = (const float*)d_in[2];
    const float* bp = (const float*)d_in[3];
    const float* Wa = (const float*)d_in[4];
    const float* ba = (const float*)d_in[5];
    float* out = (float*)d_out;

    const size_t BTC = (size_t)MROWS * CDIM;
    float* state_out = ((size_t)out_size >= BTC + (size_t)BBATCH * CDIM)
                       ? out + BTC : nullptr;

    // Unconditional (no static guards): idempotent, not a stream op, capture-safe.
    cudaFuncSetAttribute(gemm_hmma_split,
                         cudaFuncAttributeMaxDynamicSharedMemorySize, SMEM_DYN);

    convert_x<<<8192, 256>>>(x);
    convert_w<<<dim3(512, 2), 256>>>(Wp, Wa);
    gemm_hmma_split<<<dim3(MROWS / TM, 16), 128, SMEM_DYN>>>(bp, ba);
    scan_kernel<<<(BBATCH * CDIM) / 64, 64>>>(st, out, state_out);
}